// round 1
// baseline (speedup 1.0000x reference)
#include <cuda_runtime.h>
#include <stdint.h>

// ---------------------------------------------------------------------------
// ExpertBuffer fetch_on_demand: cache[slot_ids[i]] <- src[expert_ids[i]]
// for 4 parameter tensors. Pure HBM-bound gather+scatter.
//
// Inputs (metadata order):
//   0: w13_src        [E_TOTAL, 2*INTER, HIDDEN]  f32
//   1: w13_bias_src   [E_TOTAL, 2*INTER]          f32
//   2: w2_src         [E_TOTAL, HIDDEN, INTER]    f32
//   3: w2_bias_src    [E_TOTAL, HIDDEN]           f32
//   4: w13_cache      [E_CACHE, 2*INTER, HIDDEN]  f32
//   5: w13_bias_cache [E_CACHE, 2*INTER]          f32
//   6: w2_cache       [E_CACHE, HIDDEN, INTER]    f32
//   7: w2_bias_cache  [E_CACHE, HIDDEN]           f32
//   8: expert_ids     [E_CACHE] i32
//   9: slot_ids       [E_CACHE] i32
//
// Output: concat of the 4 updated cache tensors (f32).
// ---------------------------------------------------------------------------

#define MAX_SLOTS 1024

// slot -> source expert id, or -1 if the slot isn't written (keep cache value)
__device__ int g_slot_src[MAX_SLOTS];

__global__ void build_slot_map_kernel(const int* __restrict__ expert_ids,
                                      const int* __restrict__ slot_ids,
                                      int n_pairs, int n_slots) {
    if (blockIdx.x == 0 && threadIdx.x == 0) {
        for (int s = 0; s < n_slots; ++s) g_slot_src[s] = -1;
        // Sequential scatter: later pairs overwrite earlier ones (last-wins),
        // matching the reference's indexed scatter semantics.
        for (int i = 0; i < n_pairs; ++i) {
            int s = slot_ids[i];
            if (s >= 0 && s < n_slots) g_slot_src[s] = expert_ids[i];
        }
    }
}

// Copy one region: out[s, :] = (mapped ? src[e, :] : cache[s, :]) for all slots.
// Vectorized float4, fully coalesced. per4 = floats-per-expert / 4.
__global__ void gather_copy_kernel(const float4* __restrict__ src,
                                   const float4* __restrict__ cache,
                                   float4* __restrict__ out,
                                   long per4, int n_slots) {
    long idx = (long)blockIdx.x * blockDim.x + threadIdx.x;
    long total = per4 * (long)n_slots;
    if (idx >= total) return;
    int  s   = (int)(idx / per4);
    long off = idx - (long)s * per4;
    int  e   = g_slot_src[s];
    const float4* base = (e >= 0) ? (src + (long)e * per4)
                                  : (cache + (long)s * per4);
    out[idx] = base[off];
}

static inline void launch_region(const void* src, const void* cache, void* out,
                                 long per_floats, int n_slots,
                                 cudaStream_t stream) {
    long per4 = per_floats >> 2;           // all per-expert sizes are %4 == 0
    long total = per4 * (long)n_slots;
    int threads = 256;
    long blocks = (total + threads - 1) / threads;
    gather_copy_kernel<<<(unsigned)blocks, threads, 0, stream>>>(
        (const float4*)src, (const float4*)cache, (float4*)out, per4, n_slots);
}

extern "C" void kernel_launch(void* const* d_in, const int* in_sizes, int n_in,
                              void* d_out, int out_size) {
    const float* w13_src    = (const float*)d_in[0];
    const float* w13b_src   = (const float*)d_in[1];
    const float* w2_src     = (const float*)d_in[2];
    const float* w2b_src    = (const float*)d_in[3];
    const float* w13_cache  = (const float*)d_in[4];
    const float* w13b_cache = (const float*)d_in[5];
    const float* w2_cache   = (const float*)d_in[6];
    const float* w2b_cache  = (const float*)d_in[7];
    const int*   expert_ids = (const int*)d_in[8];
    const int*   slot_ids   = (const int*)d_in[9];

    int n_pairs = in_sizes[8];              // E_CACHE pairs
    int n_slots = in_sizes[9];              // number of cache slots

    long n13  = in_sizes[4];                // total floats in w13_cache
    long nb13 = in_sizes[5];
    long n2   = in_sizes[6];
    long nb2  = in_sizes[7];

    long per13  = n13  / n_slots;           // 2*INTER*HIDDEN
    long perb13 = nb13 / n_slots;           // 2*INTER
    long per2   = n2   / n_slots;           // HIDDEN*INTER
    long perb2  = nb2  / n_slots;           // HIDDEN

    float* out = (float*)d_out;
    cudaStream_t stream = 0;

    build_slot_map_kernel<<<1, 32, 0, stream>>>(expert_ids, slot_ids,
                                                n_pairs, n_slots);

    // Output layout: [w13_cache | w13_bias_cache | w2_cache | w2_bias_cache]
    long off = 0;
    launch_region(w13_src,  w13_cache,  out + off, per13,  n_slots, stream); off += n13;
    launch_region(w13b_src, w13b_cache, out + off, perb13, n_slots, stream); off += nb13;
    launch_region(w2_src,   w2_cache,   out + off, per2,   n_slots, stream); off += n2;
    launch_region(w2b_src,  w2b_cache,  out + off, perb2,  n_slots, stream);
}